// round 12
// baseline (speedup 1.0000x reference)
#include <cuda_runtime.h>
#include <math.h>

#define BATCH  64
#define LSUB   512
#define SWORDS 512
#define HID    768
#define NC     9
#define NWORDS (BATCH * SWORDS)
#define NSM    148
#define WPB    4                      // warps per block
#define ROWB   3072                   // bytes per subword row
#define SLOT_B (3 * ROWB)             // 9216 per word
#define PAIR_B (2 * SLOT_B)           // 18432 per pair
#define BUF_B  (2 * PAIR_B)           // 36864 per warp (double buffer)
#define DYN_B  (WPB * BUF_B)          // 147456

typedef unsigned long long u64;

__device__ float g_Wt[NC * HID];
__device__ int   g_ls[NWORDS];        // (start<<2)|len
__device__ int   g_widx[NWORDS];      // compacted valid word ids
__device__ int   g_total;
__device__ int   g_alloc;             // zero-init; self-cleaned
__device__ int   g_done0;
__device__ float g_loss;
__device__ int   g_cnt;
__device__ int   g_done;

__device__ __forceinline__ u64 fma2(u64 a, u64 b, u64 c) {
    u64 d; asm("fma.rn.f32x2 %0,%1,%2,%3;" : "=l"(d) : "l"(a), "l"(b), "l"(c)); return d;
}
__device__ __forceinline__ u64 add2(u64 a, u64 b) {
    u64 d; asm("add.rn.f32x2 %0,%1,%2;" : "=l"(d) : "l"(a), "l"(b)); return d;
}
__device__ __forceinline__ float upk_sum(u64 v) {
    float lo, hi; asm("mov.b64 {%0,%1},%2;" : "=f"(lo), "=f"(hi) : "l"(v)); return lo + hi;
}
__device__ __forceinline__ void cpa16(unsigned dst, const void* src) {
    asm volatile("cp.async.cg.shared.global [%0], [%1], 16;" :: "r"(dst), "l"(src));
}
#define CP_COMMIT() asm volatile("cp.async.commit_group;" ::: "memory")
#define CP_WAIT1()  asm volatile("cp.async.wait_group 1;" ::: "memory")

// ---------------------------------------------------------------------------
// Setup (unchanged from R11): scan -> g_ls, compaction -> g_widx/g_total,
// W transpose -> g_Wt, default preds, self-cleaning counters.
// ---------------------------------------------------------------------------
__global__ void __launch_bounds__(256) setup_kernel(
    const int* __restrict__ ids_lens, const float* __restrict__ W,
    const float* __restrict__ bias, float* __restrict__ out)
{
    __shared__ int s_comb[8];
    __shared__ int s_off;
    const int b = blockIdx.x, tid = threadIdx.x;
    const int lane = tid & 31, warp = tid >> 5;

    int2 lp = ((const int2*)(ids_lens + b * SWORDS))[tid];
    int f0 = (lp.x > 0), f1 = (lp.y > 0);
    int comb = ((lp.x + lp.y) << 16) | (f0 + f1);
    int inc = comb;
#pragma unroll
    for (int off = 1; off < 32; off <<= 1) {
        int n = __shfl_up_sync(0xffffffffu, inc, off);
        if (lane >= off) inc += n;
    }
    int lane_ex = inc - comb;
    if (lane == 31) s_comb[warp] = inc;
    __syncthreads();
    int wbase = 0;
#pragma unroll
    for (int i = 0; i < 8; i++) if (i < warp) wbase += s_comb[i];
    int ex = wbase + lane_ex;
    int st0 = ex >> 16;
    int vx  = ex & 0xffff;

    const int base = b * SWORDS + 2 * tid;
    g_ls[base]     = (st0 << 2) | lp.x;
    g_ls[base + 1] = ((st0 + lp.x) << 2) | lp.y;

    if (tid == 0) {
        int t = 0;
#pragma unroll
        for (int i = 0; i < 8; i++) t += s_comb[i];
        s_off = atomicAdd(&g_alloc, t & 0xffff);
    }
    __syncthreads();
    int pos = s_off + vx;
    if (f0) g_widx[pos]      = base;
    if (f1) g_widx[pos + f0] = base + 1;

    {
        float m = -1e30f; int am = 0;
#pragma unroll
        for (int c = 0; c < NC; c++) { float v = bias[c]; if (v > m) { m = v; am = c; } }
        out[1 + base] = (float)am; out[1 + base + 1] = (float)am;
    }
    if (tid < 12 * NC) {
        int h = b * 12 + tid / NC;
        int c = tid - (tid / NC) * NC;
        g_Wt[c * HID + h] = W[h * NC + c];
    }
    if (tid == 0) {
        __threadfence();
        int old = atomicAdd(&g_done0, 1);
        if (old == BATCH - 1) {
            g_total = atomicAdd(&g_alloc, 0);
            atomicExch(&g_alloc, 0);
            atomicExch(&g_done0, 0);
        }
    }
}

// ---------------------------------------------------------------------------
// Main: 148 blocks x 128 threads (1/SM). Each warp owns a private
// double-buffered pair slot; cp.async stages pair i+1 while computing pair i
// from shared. No block-level sync in the loop.
// ---------------------------------------------------------------------------
__global__ void __launch_bounds__(128) main_kernel(
    const float* __restrict__ x,
    const float* __restrict__ bias,
    const int*   __restrict__ label_ids,
    float*       __restrict__ out)
{
    extern __shared__ char dbuf[];        // WPB * 36864
    __shared__ float Ws[NC * HID];
    __shared__ float sb[NC];
    __shared__ float s_loss;
    __shared__ int   s_cnt;

    const int tid  = threadIdx.x;
    const int lane = tid & 31;
    const int warp = tid >> 5;

    {
        const float4* src = (const float4*)g_Wt;
        float4*       dst = (float4*)Ws;
        for (int i = tid; i < (NC * HID) / 4; i += 128) dst[i] = src[i];
    }
    if (tid < NC) sb[tid] = bias[tid];
    if (tid == 0) { s_loss = 0.0f; s_cnt = 0; }
    __syncthreads();

    const int total  = g_total;
    const int npairs = (total + 1) >> 1;
    const int gw = blockIdx.x * WPB + warp;
    const int nw = NSM * WPB;

    char* mybuf = dbuf + warp * BUF_B;
    const unsigned mybuf_u = (unsigned)__cvta_generic_to_shared(mybuf);
    const int2* widx2 = (const int2*)g_widx;

    // meta regs: current and next
    int cw0, cw1, cls0, cls1;

    auto loadmeta = [&](int p, int& w0, int& w1, int& ls0, int& ls1) {
        w0 = -1; w1 = -1; ls0 = 0; ls1 = 0;
        if (p < npairs) {
            int2 wp = widx2[p];
            w0 = wp.x;
            ls0 = g_ls[wp.x];
            if (2 * p + 1 < total) { w1 = wp.y; ls1 = g_ls[wp.y]; }
        }
    };

    auto stage = [&](int w0, int w1, int ls0, int ls1, int bi) {
        unsigned dst = mybuf_u + bi * PAIR_B;
#pragma unroll
        for (int k = 0; k < 2; k++) {
            int w  = k ? w1 : w0;
            int ls = k ? ls1 : ls0;
            int len = (w >= 0) ? (ls & 3) : 0;
            int st  = ls >> 2;
            int batch = w >> 9;
            const char* src = (const char*)(x + ((size_t)(batch * LSUB + st)) * HID);
            unsigned d = dst + k * SLOT_B + lane * 16;
            const char* s = src + lane * 16;
#pragma unroll
            for (int r = 0; r < 3; r++) {
                if (len > r) {
#pragma unroll
                    for (int ch = 0; ch < 6; ch++)
                        cpa16(d + r * ROWB + ch * 512, s + r * ROWB + ch * 512);
                }
            }
        }
    };

    // prologue
    int p = gw;
    loadmeta(p, cw0, cw1, cls0, cls1);
    stage(cw0, cw1, cls0, cls1, 0);
    CP_COMMIT();

    float lloss = 0.0f;
    int   lcnt  = 0;
    const ulonglong2 z2 = make_ulonglong2(0ull, 0ull);

    int i = 0;
#pragma unroll 1
    while (p < npairs) {
        int pn = p + nw;
        int nw0, nw1, nls0, nls1;
        loadmeta(pn, nw0, nw1, nls0, nls1);
        stage(nw0, nw1, nls0, nls1, (i + 1) & 1);
        CP_COMMIT();
        CP_WAIT1();                    // current pair's copies landed
        __syncwarp();

        {
            int bi = i & 1;
            int len0 = (cw0 >= 0) ? (cls0 & 3) : 0;
            int len1 = (cw1 >= 0) ? (cls1 & 3) : 0;
            const char* p0 = mybuf + bi * PAIR_B;
            const char* p1 = p0 + SLOT_B;

            u64 acc0[NC], acc1[NC];
#pragma unroll
            for (int c = 0; c < NC; c++) { acc0[c] = 0ull; acc1[c] = 0ull; }

#pragma unroll
            for (int g = 0; g < 6; g++) {
                int o = (g * 32 + lane) * 16;
                ulonglong2 a0 = (len0 > 0) ? *(const ulonglong2*)(p0 + o)            : z2;
                ulonglong2 a1 = (len0 > 1) ? *(const ulonglong2*)(p0 + ROWB + o)     : z2;
                ulonglong2 a2 = (len0 > 2) ? *(const ulonglong2*)(p0 + 2 * ROWB + o) : z2;
                ulonglong2 c0 = (len1 > 0) ? *(const ulonglong2*)(p1 + o)            : z2;
                ulonglong2 c1 = (len1 > 1) ? *(const ulonglong2*)(p1 + ROWB + o)     : z2;
                ulonglong2 c2 = (len1 > 2) ? *(const ulonglong2*)(p1 + 2 * ROWB + o) : z2;

                u64 v0l = add2(a0.x, add2(a1.x, a2.x));
                u64 v0h = add2(a0.y, add2(a1.y, a2.y));
                u64 v1l = add2(c0.x, add2(c1.x, c2.x));
                u64 v1h = add2(c0.y, add2(c1.y, c2.y));

                int hb = g * 128 + lane * 4;
#pragma unroll
                for (int c = 0; c < NC; c++) {
                    ulonglong2 wc = *(const ulonglong2*)&Ws[c * HID + hb];
                    acc0[c] = fma2(v0l, wc.x, acc0[c]);
                    acc0[c] = fma2(v0h, wc.y, acc0[c]);
                    acc1[c] = fma2(v1l, wc.x, acc1[c]);
                    acc1[c] = fma2(v1h, wc.y, acc1[c]);
                }
            }

            // split reduce: word0 -> lanes 0-15, word1 -> lanes 16-31
            float v[NC];
#pragma unroll
            for (int c = 0; c < NC; c++) {
                float s0 = upk_sum(acc0[c]);
                float s1 = upk_sum(acc1[c]);
                float keep = (lane < 16) ? s0 : s1;
                float give = (lane < 16) ? s1 : s0;
                v[c] = keep + __shfl_xor_sync(0xffffffffu, give, 16);
            }
#pragma unroll
            for (int c = 0; c < NC; c++) {
#pragma unroll
                for (int off = 8; off; off >>= 1)
                    v[c] += __shfl_xor_sync(0xffffffffu, v[c], off);
            }

            if ((lane == 0 && len0 > 0) || (lane == 16 && len1 > 0)) {
                int   w   = (lane == 0) ? cw0 : cw1;
                int   len = (lane == 0) ? len0 : len1;
                float inv = 1.0f / (float)len;
                float lg[NC];
                float m = -1e30f; int am = 0;
#pragma unroll
                for (int c = 0; c < NC; c++) {
                    lg[c] = fmaf(v[c], inv, sb[c]);
                    if (lg[c] > m) { m = lg[c]; am = c; }
                }
                out[1 + w] = (float)am;
                float sum = 0.0f;
#pragma unroll
                for (int c = 0; c < NC; c++) sum += __expf(lg[c] - m);
                int lab = label_ids[w];
                lab = lab < 0 ? 0 : (lab > NC - 1 ? NC - 1 : lab);
                lloss += -(lg[lab] - m - __logf(sum));
                lcnt  += 1;
            }
        }

        p = pn; cw0 = nw0; cw1 = nw1; cls0 = nls0; cls1 = nls1;
        i++;
    }

    lloss += __shfl_xor_sync(0xffffffffu, lloss, 16);
    lcnt  += __shfl_xor_sync(0xffffffffu, lcnt,  16);
    if (lane == 0 && lcnt > 0) {
        atomicAdd(&s_loss, lloss);
        atomicAdd(&s_cnt, lcnt);
    }
    __syncthreads();

    if (tid == 0) {
        if (s_cnt > 0) {
            atomicAdd(&g_loss, s_loss);
            atomicAdd(&g_cnt, s_cnt);
        }
        __threadfence();
        int old = atomicAdd(&g_done, 1);
        if (old == NSM - 1) {
            float lv = atomicAdd(&g_loss, 0.0f);
            int   cv = atomicAdd(&g_cnt, 0);
            out[0] = lv / fmaxf((float)cv, 1.0f);
            g_loss = 0.0f; g_cnt = 0;
            atomicExch(&g_done, 0);
        }
    }
}

extern "C" void kernel_launch(void* const* d_in, const int* in_sizes, int n_in,
                              void* d_out, int out_size) {
    const float* bert_out  = (const float*)d_in[0];
    const float* W         = (const float*)d_in[1];
    const float* b         = (const float*)d_in[2];
    const int*   ids_lens  = (const int*)d_in[4];
    const int*   label_ids = (const int*)d_in[5];
    float* out = (float*)d_out;

    cudaFuncSetAttribute(main_kernel, cudaFuncAttributeMaxDynamicSharedMemorySize, DYN_B);

    setup_kernel<<<BATCH, 256>>>(ids_lens, W, b, out);
    main_kernel<<<NSM, 128, DYN_B>>>(bert_out, b, label_ids, out);
}

// round 13
// speedup vs baseline: 1.5830x; 1.5830x over previous
#include <cuda_runtime.h>
#include <math.h>

#define BATCH  64
#define LSUB   512
#define SWORDS 512
#define HID    768
#define NC     9
#define NWORDS (BATCH * SWORDS)
#define MGRID  296          // 2 blocks/SM, exactly one resident wave

typedef unsigned long long u64;

__device__ int   g_ls[NWORDS];         // (start<<2)|len
__device__ int   g_widx[NWORDS];       // compacted valid word ids
__device__ int   g_total;
__device__ int   g_alloc;              // zero-init; self-cleaned
__device__ int   g_done0;
__device__ int   g_phase;
__device__ float g_loss;
__device__ int   g_cnt;
__device__ int   g_done;

__device__ __forceinline__ u64 fma2(u64 a, u64 b, u64 c) {
    u64 d; asm("fma.rn.f32x2 %0,%1,%2,%3;" : "=l"(d) : "l"(a), "l"(b), "l"(c)); return d;
}
__device__ __forceinline__ u64 add2(u64 a, u64 b) {
    u64 d; asm("add.rn.f32x2 %0,%1,%2;" : "=l"(d) : "l"(a), "l"(b)); return d;
}
__device__ __forceinline__ float upk_sum(u64 v) {
    float lo, hi; asm("mov.b64 {%0,%1},%2;" : "=f"(lo), "=f"(hi) : "l"(v)); return lo + hi;
}
__device__ __forceinline__ void pf2(const void* p) {
    asm volatile("prefetch.global.L2 [%0];" :: "l"(p));
}

// ---------------------------------------------------------------------------
// Fused kernel: 296 blocks x 256 threads, one wave.
// Phase 0 (blocks 0-63): per-batch scan -> g_ls, compaction -> g_widx,
//   default preds. All blocks meanwhile transpose W into shared. Flag-spin,
//   then all blocks compute valid word-pairs with f32x2 math + L2 prefetch.
// ---------------------------------------------------------------------------
__global__ void __launch_bounds__(256, 2) main_kernel(
    const float* __restrict__ x,        // [B, L, H]
    const float* __restrict__ W,        // [H, C]
    const float* __restrict__ bias,     // [C]
    const int*   __restrict__ ids_lens, // [B, S]
    const int*   __restrict__ label_ids,
    float*       __restrict__ out)      // out[0]=loss, out[1..]=pred
{
    __shared__ float Ws[NC * HID];      // Ws[c*HID + h]
    __shared__ float sb[NC];
    __shared__ int   s_comb[8];
    __shared__ int   s_off;
    __shared__ float s_loss;
    __shared__ int   s_cnt;

    const int tid  = threadIdx.x;
    const int lane = tid & 31;
    const int warp = tid >> 5;

    // ---- W transpose directly into shared (no global staging) ----
    for (int j = tid; j < NC * HID; j += 256) {
        int c = j / HID;
        int h = j - c * HID;
        Ws[j] = W[h * NC + c];
    }
    if (tid < NC) sb[tid] = bias[tid];
    if (tid == 0) { s_loss = 0.0f; s_cnt = 0; }

    // ---- phase 0: first 64 blocks do per-batch setup ----
    if (blockIdx.x < BATCH) {
        const int b = blockIdx.x;
        int2 lp = ((const int2*)(ids_lens + b * SWORDS))[tid];
        int f0 = (lp.x > 0), f1 = (lp.y > 0);
        int comb = ((lp.x + lp.y) << 16) | (f0 + f1);
        int inc = comb;
#pragma unroll
        for (int off = 1; off < 32; off <<= 1) {
            int n = __shfl_up_sync(0xffffffffu, inc, off);
            if (lane >= off) inc += n;
        }
        int lane_ex = inc - comb;
        if (lane == 31) s_comb[warp] = inc;
        __syncthreads();
        int wbase = 0;
#pragma unroll
        for (int i = 0; i < 8; i++) if (i < warp) wbase += s_comb[i];
        int ex = wbase + lane_ex;
        int st0 = ex >> 16;
        int vx  = ex & 0xffff;

        const int base = b * SWORDS + 2 * tid;
        g_ls[base]     = (st0 << 2) | lp.x;
        g_ls[base + 1] = ((st0 + lp.x) << 2) | lp.y;

        if (tid == 0) {
            int t = 0;
#pragma unroll
            for (int i = 0; i < 8; i++) t += s_comb[i];
            s_off = atomicAdd(&g_alloc, t & 0xffff);
        }
        __syncthreads();
        int pos = s_off + vx;
        if (f0) g_widx[pos]      = base;
        if (f1) g_widx[pos + f0] = base + 1;

        // default preds = argmax(bias)
        {
            float m = -1e30f; int am = 0;
#pragma unroll
            for (int c = 0; c < NC; c++) { float v = sb[c]; if (v > m) { m = v; am = c; } }
            out[1 + base] = (float)am; out[1 + base + 1] = (float)am;
        }
        __syncthreads();
        if (tid == 0) {
            __threadfence();
            int old = atomicAdd(&g_done0, 1);
            if (old == BATCH - 1) {
                g_total = atomicAdd(&g_alloc, 0);   // publish BEFORE phase bump
                __threadfence();
            }
            atomicAdd(&g_phase, 1);
        }
    }

    // ---- spin until setup published (all 296 blocks resident: safe) ----
    if (tid == 0) {
        while (atomicAdd(&g_phase, 0) < BATCH) __nanosleep(64);
    }
    __syncthreads();

    const int total  = g_total;
    const int npairs = (total + 1) >> 1;
    const int gw = blockIdx.x * 8 + warp;
    const int nw = MGRID * 8;

    float lloss = 0.0f;
    int   lcnt  = 0;

    const ulonglong2 z2 = make_ulonglong2(0ull, 0ull);
    const int RS = HID / 4;
    const int2* widx2 = (const int2*)g_widx;

    int p = gw;
    int2 wp = make_int2(0, 0);
    int lsa = 0, lsb = 0;
    if (p < npairs) {
        wp  = widx2[p];
        lsa = g_ls[wp.x];
        if (2 * p + 1 < total) lsb = g_ls[wp.y];
    }

#pragma unroll 1
    while (p < npairs) {
        // prefetch next iteration's metadata
        int pn = p + nw;
        int2 wpn = wp; int lsan = lsa, lsbn = lsb;
        if (pn < npairs) {
            wpn  = widx2[pn];
            lsan = g_ls[wpn.x];
            lsbn = (2 * pn + 1 < total) ? g_ls[wpn.y] : 0;
        }

        // L2 prefetch next pair's rows (no regs held, no scoreboard)
        {
            int ln0 = lsan & 3, ln1 = lsbn & 3;
            const char* nb0 = (const char*)(x + ((size_t)((wpn.x >> 9) * LSUB + (lsan >> 2))) * HID);
            const char* nb1 = (const char*)(x + ((size_t)((wpn.y >> 9) * LSUB + (lsbn >> 2))) * HID);
            int off = (lane < 24) ? lane * 128 : (lane - 24) * 128;
            if (ln0 > 0) pf2(nb0 + off);
            if (ln0 > 1) pf2(nb0 + 3072 + off);
            if (ln0 > 2) pf2(nb0 + 6144 + off);
            if (ln1 > 0) pf2(nb1 + off);
            if (ln1 > 1) pf2(nb1 + 3072 + off);
            if (ln1 > 2) pf2(nb1 + 6144 + off);
        }

        int w0 = wp.x, w1 = wp.y;
        bool act1 = (2 * p + 1 < total);
        int len0 = lsa & 3, len1 = lsb & 3;
        int st0  = lsa >> 2, st1 = lsb >> 2;
        int b0 = w0 >> 9, b1 = w1 >> 9;

        const ulonglong2* base0 = (const ulonglong2*)(x + ((size_t)(b0 * LSUB + st0)) * HID);
        const ulonglong2* base1 = (const ulonglong2*)(x + ((size_t)(b1 * LSUB + st1)) * HID);

        u64 acc0[NC], acc1[NC];
#pragma unroll
        for (int c = 0; c < NC; c++) { acc0[c] = 0ull; acc1[c] = 0ull; }

#pragma unroll
        for (int g = 0; g < 6; g++) {
            int idx = g * 32 + lane;
            ulonglong2 a0 = (len0 > 0) ? base0[idx]          : z2;
            ulonglong2 a1 = (len0 > 1) ? base0[idx + RS]     : z2;
            ulonglong2 a2 = (len0 > 2) ? base0[idx + 2 * RS] : z2;
            ulonglong2 c0 = (len1 > 0) ? base1[idx]          : z2;
            ulonglong2 c1 = (len1 > 1) ? base1[idx + RS]     : z2;
            ulonglong2 c2 = (len1 > 2) ? base1[idx + 2 * RS] : z2;

            u64 v0l = add2(a0.x, add2(a1.x, a2.x));
            u64 v0h = add2(a0.y, add2(a1.y, a2.y));
            u64 v1l = add2(c0.x, add2(c1.x, c2.x));
            u64 v1h = add2(c0.y, add2(c1.y, c2.y));

            int hb = g * 128 + lane * 4;
#pragma unroll
            for (int c = 0; c < NC; c++) {
                ulonglong2 wc = *(const ulonglong2*)&Ws[c * HID + hb];
                acc0[c] = fma2(v0l, wc.x, acc0[c]);
                acc0[c] = fma2(v0h, wc.y, acc0[c]);
                acc1[c] = fma2(v1l, wc.x, acc1[c]);
                acc1[c] = fma2(v1h, wc.y, acc1[c]);
            }
        }

        // split reduce: word0 -> lanes 0-15, word1 -> lanes 16-31
        float v[NC];
#pragma unroll
        for (int c = 0; c < NC; c++) {
            float s0 = upk_sum(acc0[c]);
            float s1 = upk_sum(acc1[c]);
            float keep = (lane < 16) ? s0 : s1;
            float give = (lane < 16) ? s1 : s0;
            v[c] = keep + __shfl_xor_sync(0xffffffffu, give, 16);
        }
#pragma unroll
        for (int c = 0; c < NC; c++) {
#pragma unroll
            for (int off = 8; off; off >>= 1)
                v[c] += __shfl_xor_sync(0xffffffffu, v[c], off);
        }

        // two-lane parallel epilogue
        if (lane == 0 || (lane == 16 && act1)) {
            int   w   = (lane == 0) ? w0 : w1;
            int   len = (lane == 0) ? len0 : len1;
            float inv = 1.0f / (float)len;
            float lg[NC];
            float m = -1e30f; int am = 0;
#pragma unroll
            for (int c = 0; c < NC; c++) {
                lg[c] = fmaf(v[c], inv, sb[c]);
                if (lg[c] > m) { m = lg[c]; am = c; }
            }
            out[1 + w] = (float)am;
            float sum = 0.0f;
#pragma unroll
            for (int c = 0; c < NC; c++) sum += __expf(lg[c] - m);
            int lab = label_ids[w];
            lab = lab < 0 ? 0 : (lab > NC - 1 ? NC - 1 : lab);
            lloss += -(lg[lab] - m - __logf(sum));
            lcnt  += 1;
        }

        p = pn; wp = wpn; lsa = lsan; lsb = lsbn;
    }

    lloss += __shfl_xor_sync(0xffffffffu, lloss, 16);
    lcnt  += __shfl_xor_sync(0xffffffffu, lcnt,  16);
    if (lane == 0 && lcnt > 0) {
        atomicAdd(&s_loss, lloss);
        atomicAdd(&s_cnt, lcnt);
    }
    __syncthreads();

    if (tid == 0) {
        if (s_cnt > 0) {
            atomicAdd(&g_loss, s_loss);
            atomicAdd(&g_cnt, s_cnt);
        }
        __threadfence();
        int old = atomicAdd(&g_done, 1);
        if (old == MGRID - 1) {
            float lv = atomicAdd(&g_loss, 0.0f);
            int   cv = atomicAdd(&g_cnt, 0);
            out[0] = lv / fmaxf((float)cv, 1.0f);
            // self-clean ALL state for the next graph replay
            g_loss = 0.0f; g_cnt = 0;
            atomicExch(&g_alloc, 0);
            atomicExch(&g_done0, 0);
            atomicExch(&g_phase, 0);
            atomicExch(&g_done, 0);
        }
    }
}

extern "C" void kernel_launch(void* const* d_in, const int* in_sizes, int n_in,
                              void* d_out, int out_size) {
    const float* bert_out  = (const float*)d_in[0];
    const float* W         = (const float*)d_in[1];
    const float* b         = (const float*)d_in[2];
    const int*   ids_lens  = (const int*)d_in[4];
    const int*   label_ids = (const int*)d_in[5];
    float* out = (float*)d_out;

    main_kernel<<<MGRID, 256>>>(bert_out, W, b, ids_lens, label_ids, out);
}